// round 16
// baseline (speedup 1.0000x reference)
#include <cuda_runtime.h>
#include <cuda_bf16.h>

// x shape (64, 20, 64, 32, 32) fp32 ; B=64, CHI=20, D=65536
#define B_    64
#define CHI_  20
#define D_    65536
#define WB_   8                    // batches per wave (41.9 MB -> L2 resident)
#define NW_   (B_ / WB_)           // 8 waves
#define SBLK_ 128                  // d-slice blocks per batch (grid 1024/wave)
#define POS_  128                  // float4 positions per block (512 floats)

// Scratch (no cudaMalloc). g_part rows padded to 32 floats (128B).
__device__ float g_part[B_][SBLK_][32];  // partial scores per (batch, slice)

// ---------------------------------------------------------------------------
// scores pass (per wave): 1024 blocks x 256 threads (262k threads/wave).
// Rows split across half-blocks: threads 0-127 -> rows 0-9, threads
// 128-255 -> rows 10-19. Each thread: 1 last-row float4 (L1/L2 hit for the
// second half) + 10 independent row loads (MLP~10, 2x threads vs R15).
// ---------------------------------------------------------------------------
__global__ __launch_bounds__(256)
void scores_kernel(const float* __restrict__ x, int wave) {
    const int b_local = blockIdx.x >> 7;        // / SBLK_
    const int blk     = blockIdx.x & (SBLK_ - 1);
    const int b       = wave * WB_ + b_local;
    const size_t base = (size_t)b * CHI_ * D_;
    const int tid     = threadIdx.x;
    const int lane    = tid & 31;
    const int wid     = tid >> 5;
    const int csplit  = tid >> 7;               // 0: rows 0-9, 1: rows 10-19
    const int pos     = tid & (POS_ - 1);

    const int f4idx = blk * POS_ + pos;         // float4 index within a row
    const float4 lr = __ldg(
        reinterpret_cast<const float4*>(x + base + (size_t)(CHI_ - 1) * D_) + f4idx);

    // 10 independent dot contributions for this half-block's rows
    float acc[10];
    #pragma unroll
    for (int cc = 0; cc < 10; cc++) {
        const int c = csplit * 10 + cc;
        float4 v = __ldg(
            reinterpret_cast<const float4*>(x + base + (size_t)c * D_) + f4idx);
        float a = v.x * lr.x;
        a = fmaf(v.y, lr.y, a);
        a = fmaf(v.z, lr.z, a);
        a = fmaf(v.w, lr.w, a);
        acc[cc] = a;
    }

    // warp-reduce the 10 accumulators (row set is uniform within a warp)
    #pragma unroll
    for (int cc = 0; cc < 10; cc++) {
        #pragma unroll
        for (int off = 16; off > 0; off >>= 1)
            acc[cc] += __shfl_down_sync(0xFFFFFFFFu, acc[cc], off);
    }
    __shared__ float s_red[8][10];              // warps 0-3: rows 0-9; 4-7: 10-19
    if (lane == 0) {
        #pragma unroll
        for (int cc = 0; cc < 10; cc++) s_red[wid][cc] = acc[cc];
    }
    __syncthreads();

    if (tid < CHI_) {
        const int w0 = (tid < 10) ? 0 : 4;
        const int cc = (tid < 10) ? tid : (tid - 10);
        float v = s_red[w0][cc] + s_red[w0 + 1][cc]
                + s_red[w0 + 2][cc] + s_red[w0 + 3][cc];   // fixed order
        g_part[b][blk][tid] = v;
    }
}

// ---------------------------------------------------------------------------
// out pass (per wave): warp 0 of every block recomputes the softmax from
// g_part (16KB, L2-hot; fixed order -> identical & deterministic everywhere),
// then out[b,d] = sum_c flat[b, d*20+c] * alpha[b,c] from L2-resident lines.
// __ldcs marks lines evict-first after this last use.
// ---------------------------------------------------------------------------
__global__ __launch_bounds__(256)
void out_kernel(const float* __restrict__ x, float* __restrict__ out, int wave) {
    __shared__ float alpha_s[CHI_];
    const int b = wave * WB_ + blockIdx.y;

    if (threadIdx.x < 32) {
        const int lane = threadIdx.x;
        float s = 0.0f;
        if (lane < CHI_) {
            #pragma unroll
            for (int blk = 0; blk < SBLK_; blk++)
                s += g_part[b][blk][lane];               // fixed order
            s *= (1.0f / (float)CHI_);
        }
        float sv = (lane < CHI_) ? s : -1e30f;
        #pragma unroll
        for (int off = 16; off > 0; off >>= 1)
            sv = fmaxf(sv, __shfl_xor_sync(0xFFFFFFFFu, sv, off));
        float e = (lane < CHI_) ? __expf(s - sv) : 0.0f;
        float z = e;
        #pragma unroll
        for (int off = 16; off > 0; off >>= 1)
            z += __shfl_xor_sync(0xFFFFFFFFu, z, off);
        if (lane < CHI_)
            alpha_s[lane] = e / z;
    }
    __syncthreads();

    const int d = blockIdx.x * 256 + threadIdx.x;   // gridDim.x = D/256
    const float4* __restrict__ p =
        reinterpret_cast<const float4*>(x + (size_t)b * CHI_ * D_ + (size_t)d * CHI_);

    float acc = 0.0f;
    #pragma unroll
    for (int j = 0; j < 5; j++) {
        float4 v = __ldcs(p + j);                   // L2 hit; evict-first
        acc = fmaf(v.x, alpha_s[j * 4 + 0], acc);
        acc = fmaf(v.y, alpha_s[j * 4 + 1], acc);
        acc = fmaf(v.z, alpha_s[j * 4 + 2], acc);
        acc = fmaf(v.w, alpha_s[j * 4 + 3], acc);
    }
    out[(size_t)b * D_ + d] = acc;
}

// ---------------------------------------------------------------------------
// Two-stream pipeline inside the captured graph:
//   stream0 : scores(0) scores(1) ...   (scores(w) waits out(w-2))
//   s2      : out(0) out(1) ...         (out(w) waits scores(w))
// scores(w+1) streams DRAM while out(w) drains L2; <=2 waves (84 MB) live.
// ---------------------------------------------------------------------------
extern "C" void kernel_launch(void* const* d_in, const int* in_sizes, int n_in,
                              void* d_out, int out_size) {
    const float* x   = (const float*)d_in[0];
    float*       out = (float*)d_out;

    static bool         init = false;
    static cudaStream_t s2;
    static cudaEvent_t  evS[NW_], evO[NW_];
    if (!init) {
        cudaStreamCreateWithFlags(&s2, cudaStreamNonBlocking);
        for (int i = 0; i < NW_; i++) {
            cudaEventCreateWithFlags(&evS[i], cudaEventDisableTiming);
            cudaEventCreateWithFlags(&evO[i], cudaEventDisableTiming);
        }
        init = true;
    }

    for (int w = 0; w < NW_; w++) {
        if (w >= 2)
            cudaStreamWaitEvent(0, evO[w - 2], 0);         // L2 residency throttle
        scores_kernel<<<WB_ * SBLK_, 256>>>(x, w);         // 1024 blocks
        cudaEventRecord(evS[w], 0);

        cudaStreamWaitEvent(s2, evS[w], 0);                // fork / dependency
        dim3 grid(D_ / 256, WB_);
        out_kernel<<<grid, 256, 0, s2>>>(x, out, w);
        cudaEventRecord(evO[w], s2);
    }
    cudaStreamWaitEvent(0, evO[NW_ - 1], 0);               // join
}